// round 12
// baseline (speedup 1.0000x reference)
#include <cuda_runtime.h>

#define NLAYERS 4
#define BATCH   8
#define CCH     256
#define HH      32
#define WWW     32
#define NHEADS  8
#define DHEAD   64
#define SPI     1024
#define NPIX    8192
#define NTOK    65536
#define KHH     512

// ---------------- scratch (green overlay set; no new globals) ----------------
__device__ __align__(16) float g_x[BATCH*CCH*SPI];
__device__ __align__(16) float g_keys[NLAYERS][NTOK*DHEAD];
__device__ __align__(16) float g_vals[NLAYERS][NTOK*DHEAD];
__device__ __align__(16) float g_q[NTOK*DHEAD];     // doubles as conv weight-frag scratch
__device__ __align__(16) float g_o[BATCH*KHH*SPI];
__device__ __align__(16) float g_h[BATCH*CCH*SPI];  // doubles as qkv weight-frag scratch
__device__ float g_bnsum[CCH];
__device__ float g_bnsq[CCH];

#define QKV_FRAG_SZ   131072
#define C1_FRAG_OFF   0
#define C2_FRAG_OFF   1179648

// halo geometry for 64-pixel (2-row) tiles: 4 rows x 34 cols per cin, 8 cins
#define HROW 34
#define HCIN 136
#define HTOT 1088

// ---------------- tf32 helpers ----------------
__device__ __forceinline__ unsigned f2tf(float x) {
    unsigned r;
    asm("cvt.rna.tf32.f32 %0, %1;" : "=r"(r) : "f"(x));
    return r;
}
__device__ __forceinline__ void mma8v(float (&d)[4], uint4 a, unsigned b0, unsigned b1) {
    asm volatile(
        "mma.sync.aligned.m16n8k8.row.col.f32.tf32.tf32.f32 "
        "{%0,%1,%2,%3}, {%4,%5,%6,%7}, {%8,%9}, {%0,%1,%2,%3};"
        : "+f"(d[0]), "+f"(d[1]), "+f"(d[2]), "+f"(d[3])
        : "r"(a.x), "r"(a.y), "r"(a.z), "r"(a.w), "r"(b0), "r"(b1));
}

// ---------------- weight conversion (qkv: one launch, grid.y selects matrix) ----
__global__ void wconv_qkv(const float* __restrict__ Wk, const float* __restrict__ Wq,
                          const float* __restrict__ Wv) {
    int type = blockIdx.y;
    const float* W = (type == 0) ? Wk : ((type == 1) ? Wq : Wv);
    unsigned* Wc = (unsigned*)g_h + type * QKV_FRAG_SZ;
    int idx = blockIdx.x * 256 + threadIdx.x;
    int m = idx >> 8, k = idx & 255;
    int ch = k >> 5, kc = k & 31;
    int ks = kc >> 3, c = kc & 7;
    int mt = m >> 4, rr = m & 15, gg = rr & 7;
    int lane = gg * 4 + (c & 3);
    int reg = (rr >> 3) + ((c >> 2) << 1);
    Wc[(((ch*4 + ks)*32 + mt)*32 + lane)*4 + reg] = f2tf(W[idx]);
}

__global__ void wconv(const float* __restrict__ W, int dstOff,
                      int Kdim, int CK, int NMT) {
    unsigned* Wc = (unsigned*)g_q + dstOff;
    int idx = blockIdx.x * 256 + threadIdx.x;
    int m = idx / Kdim, k = idx - m * Kdim;
    int ch = k / CK, kc = k - ch * CK;
    int ks = kc >> 3, c = kc & 7;
    int KS = CK >> 3;
    int mt = m >> 4, rr = m & 15, gg = rr & 7;
    int lane = gg * 4 + (c & 3);
    int reg = (rr >> 3) + ((c >> 2) << 1);
    Wc[(((ch*KS + ks)*NMT + mt)*32 + lane)*4 + reg] = f2tf(W[idx]);
}

// ---------------- copy in/out ----------------
__global__ void copy_in(const float* __restrict__ x) {
    int i = blockIdx.x * 256 + threadIdx.x;
    ((float4*)g_x)[i] = ((const float4*)x)[i];
}
__global__ void copy_out(float* __restrict__ out) {
    int i = blockIdx.x * 256 + threadIdx.x;
    ((float4*)out)[i] = ((const float4*)g_x)[i];
}

// ---------------- QKV 1x1 conv: double-buffered Bs, 1 sync/chunk ----------------
__global__ __launch_bounds__(256) void qkv_gemm(
    const float* __restrict__ bk, const float* __restrict__ bq, const float* __restrict__ bv,
    int l)
{
    __shared__ unsigned Bs[2][32*136];
    int tid = threadIdx.x;
    int warp = tid >> 5, lane = tid & 31;
    int g = lane >> 2, l4 = lane & 3;
    int wm = warp & 1, wn = warp >> 1;
    int by = blockIdx.y, type = by >> 2, mb = by & 3;
    const float* bt = (type == 0) ? bk : ((type == 1) ? bq : bv);
    float* outb = (type == 0) ? g_keys[l] : ((type == 1) ? g_q : g_vals[l]);
    const uint4* Ab = (const uint4*)((const unsigned*)g_h + type * QKV_FRAG_SZ);

    int pbase = blockIdx.x * 128;
    int bimg = pbase >> 10, sbase = pbase & 1023;
    const float* xin = g_x + bimg * (CCH * SPI);

    float acc[4][4][4];
#pragma unroll
    for (int mt = 0; mt < 4; mt++)
#pragma unroll
        for (int nt = 0; nt < 4; nt++)
#pragma unroll
            for (int r = 0; r < 4; r++) acc[mt][nt][r] = 0.0f;

    int bcin = tid >> 3, bseg = (tid & 7) * 16;
    const float* bbase = xin + bcin * SPI + sbase + bseg;

    float4 pb[4];
    // prologue: stage chunk 0, prefetch chunk 1
    {
        const float4* bp = (const float4*)bbase;
#pragma unroll
        for (int j = 0; j < 4; j++) pb[j] = bp[j];
#pragma unroll
        for (int j = 0; j < 4; j++) {
            float4 v = pb[j];
            uint4 u = make_uint4(f2tf(v.x), f2tf(v.y), f2tf(v.z), f2tf(v.w));
            *(uint4*)&Bs[0][bcin*136 + bseg + j*4] = u;
        }
        const float4* bp1 = (const float4*)(bbase + 32 * SPI);
#pragma unroll
        for (int j = 0; j < 4; j++) pb[j] = bp1[j];
    }
    __syncthreads();

    for (int c = 0; c < 8; c++) {
        // stage next chunk into other buffer (overlaps with MMAs below)
        if (c + 1 < 8) {
#pragma unroll
            for (int j = 0; j < 4; j++) {
                float4 v = pb[j];
                uint4 u = make_uint4(f2tf(v.x), f2tf(v.y), f2tf(v.z), f2tf(v.w));
                *(uint4*)&Bs[(c+1)&1][bcin*136 + bseg + j*4] = u;
            }
            if (c + 2 < 8) {
                const float4* bp = (const float4*)(bbase + (c+2) * 32 * SPI);
#pragma unroll
                for (int j = 0; j < 4; j++) pb[j] = bp[j];
            }
        }
        const unsigned* Bc = Bs[c&1];
#pragma unroll
        for (int ks = 0; ks < 4; ks++) {
            int abase = ((c*4 + ks)*32 + mb*8 + wm*4)*32 + lane;
            uint4 af[4];
#pragma unroll
            for (int mt = 0; mt < 4; mt++) af[mt] = Ab[abase + mt*32];
            unsigned b[4][2];
#pragma unroll
            for (int nt = 0; nt < 4; nt++) {
                int n = wn*32 + nt*8 + g;
                b[nt][0] = Bc[(ks*8 + l4)*136 + n];
                b[nt][1] = Bc[(ks*8 + l4 + 4)*136 + n];
            }
#pragma unroll
            for (int mt = 0; mt < 4; mt++)
#pragma unroll
                for (int nt = 0; nt < 4; nt++)
                    mma8v(acc[mt][nt], af[mt], b[nt][0], b[nt][1]);
        }
        __syncthreads();
    }

#pragma unroll
    for (int mt = 0; mt < 4; mt++)
#pragma unroll
        for (int half = 0; half < 2; half++) {
            int mg = mb*128 + wm*64 + mt*16 + g + half*8;
            float bias = bt[mg];
#pragma unroll
            for (int nt = 0; nt < 4; nt++) {
                int p = pbase + wn*32 + nt*8 + l4*2;
                outb[p*512 + mg]       = acc[mt][nt][half*2]     + bias;
                outb[(p+1)*512 + mg]   = acc[mt][nt][half*2 + 1] + bias;
            }
        }
}

// ---------------- attention (unchanged) ----------------
__global__ __launch_bounds__(256) void attn_kernel(int l) {
    if (blockIdx.x == 0) {
        g_bnsum[threadIdx.x] = 0.0f;
        g_bnsq[threadIdx.x] = 0.0f;
    }
    int warp = threadIdx.x >> 5, lane = threadIdx.x & 31;
    int tok = blockIdx.x * 8 + warp;

    float2 q = ((const float2*)&g_q[tok * DHEAD])[lane];
    q.x *= 0.125f; q.y *= 0.125f;

    float sc[5];
#pragma unroll 4
    for (int t = 0; t <= l; t++) {
        float2 kv = ((const float2*)&g_keys[t][tok * DHEAD])[lane];
        float p = q.x * kv.x + q.y * kv.y;
#pragma unroll
        for (int o = 16; o; o >>= 1) p += __shfl_xor_sync(0xffffffffu, p, o);
        sc[t] = p;
    }
    sc[l + 1] = 0.0f;
    int T = l + 2;

    float mx = sc[0];
    for (int t = 1; t < T; t++) mx = fmaxf(mx, sc[t]);
    float e[5], sum = 0.0f;
    for (int t = 0; t < T; t++) { e[t] = expf(sc[t] - mx); sum += e[t]; }
    float inv = 1.0f / sum;
    float a[5];
    for (int t = 0; t < T; t++) a[t] = e[t] * inv;

    if (T == 5) {
        float mn1 = fminf(fminf(a[0], a[1]), fminf(fminf(a[2], a[3]), a[4]));
        float mn2 = 1e30f; bool used = false;
        for (int t = 0; t < 5; t++) {
            if (!used && a[t] == mn1) used = true;
            else mn2 = fminf(mn2, a[t]);
        }
        float delta = mn2 + 1e-7f;
        float s2 = 0.0f;
        for (int t = 0; t < 5; t++) { a[t] = fmaxf(a[t] - delta, 0.0f); s2 += a[t]; }
        float r = 1.0f / (s2 + 1e-7f);
        for (int t = 0; t < 5; t++) a[t] *= r;
    }

    float2 oacc = make_float2(0.0f, 0.0f);
#pragma unroll 4
    for (int t = 0; t <= l; t++) {
        float2 vv = ((const float2*)&g_vals[t][tok * DHEAD])[lane];
        oacc.x += a[t] * vv.x;
        oacc.y += a[t] * vv.y;
    }

    int p = tok >> 3, head = tok & 7;
    int bimg = p >> 10, s = p & 1023;
    float* op = g_o + bimg * (KHH * SPI) + (head * DHEAD + lane * 2) * SPI + s;
    op[0]   = oacc.x;
    op[SPI] = oacc.y;
}

// ---------------- conv1: 64-pixel tiles, double-buffered halo, 1 sync/chunk ----
__global__ __launch_bounds__(256) void conv1_gemm(const float* __restrict__ bt) {
    __shared__ unsigned Hs[2][HTOT];
    int tid = threadIdx.x;
    int warp = tid >> 5, lane = tid & 31;
    int g = lane >> 2, l4 = lane & 3;
    int wm = warp & 1, wn = warp >> 1;
    int mbase = blockIdx.y * 128;
    int pbase = blockIdx.x * 64;
    int bimg = pbase >> 10, sbase = pbase & 1023;
    int r0 = sbase >> 5;
    const float* in0 = g_o + bimg * (KHH * SPI);
    const uint4* Ab = (const uint4*)((const unsigned*)g_q + C1_FRAG_OFF);
    int mtb = blockIdx.y * 8;
    int pixrow = wn >> 1, pixc0 = (wn & 1) * 16;
    int pixbase = pixrow*HROW + pixc0 + g;

    int koffA[9], koffB[9];
#pragma unroll
    for (int ks = 0; ks < 9; ks++) {
        int k = ks*8 + l4;
        int cin = k / 9, jj = k - cin*9;
        koffA[ks] = cin*HCIN + (jj/3)*HROW + (jj%3);
        k += 4; cin = k / 9; jj = k - cin*9;
        koffB[ks] = cin*HCIN + (jj/3)*HROW + (jj%3);
    }

    int hoff[5];
#pragma unroll
    for (int it = 0; it < 5; it++) {
        int idx = tid + it*256;
        hoff[it] = -1;
        if (idx < HTOT) {
            int cin = idx / HCIN, rem = idx - cin*HCIN;
            int rr = rem / HROW, cc = rem - rr*HROW;
            int yy = r0 - 1 + rr, xx = cc - 1;
            if (yy >= 0 && yy < HH && xx >= 0 && xx < WWW)
                hoff[it] = cin*SPI + yy*WWW + xx;
        }
    }

    float acc[4][2][4];
#pragma unroll
    for (int mt = 0; mt < 4; mt++)
#pragma unroll
        for (int nt = 0; nt < 2; nt++)
#pragma unroll
            for (int r = 0; r < 4; r++) acc[mt][nt][r] = 0.0f;

    float pv[5];
    // prologue: stage chunk 0 halo, prefetch chunk 1
#pragma unroll
    for (int it = 0; it < 5; it++) pv[it] = (hoff[it] >= 0) ? in0[hoff[it]] : 0.0f;
#pragma unroll
    for (int it = 0; it < 5; it++) {
        int idx = tid + it*256;
        if (idx < HTOT) Hs[0][idx] = f2tf(pv[it]);
    }
    {
        const float* nb = in0 + 8 * SPI;
#pragma unroll
        for (int it = 0; it < 5; it++) pv[it] = (hoff[it] >= 0) ? nb[hoff[it]] : 0.0f;
    }
    __syncthreads();

    for (int ch = 0; ch < 64; ch++) {
        if (ch + 1 < 64) {
#pragma unroll
            for (int it = 0; it < 5; it++) {
                int idx = tid + it*256;
                if (idx < HTOT) Hs[(ch+1)&1][idx] = f2tf(pv[it]);
            }
            if (ch + 2 < 64) {
                const float* nb = in0 + (ch + 2) * 8 * SPI;
#pragma unroll
                for (int it = 0; it < 5; it++) pv[it] = (hoff[it] >= 0) ? nb[hoff[it]] : 0.0f;
            }
        }
        const unsigned* Hc = Hs[ch&1];
#pragma unroll
        for (int ks = 0; ks < 9; ks++) {
            int abase = ((ch*9 + ks)*16 + mtb + wm*4)*32 + lane;
            uint4 af[4];
#pragma unroll
            for (int mt = 0; mt < 4; mt++) af[mt] = Ab[abase + mt*32];
            unsigned b[2][2];
#pragma unroll
            for (int nt = 0; nt < 2; nt++) {
                b[nt][0] = Hc[koffA[ks] + pixbase + nt*8];
                b[nt][1] = Hc[koffB[ks] + pixbase + nt*8];
            }
#pragma unroll
            for (int mt = 0; mt < 4; mt++)
#pragma unroll
                for (int nt = 0; nt < 2; nt++)
                    mma8v(acc[mt][nt], af[mt], b[nt][0], b[nt][1]);
        }
        __syncthreads();
    }

    float* hbase = g_h + bimg * (CCH * SPI);
#pragma unroll
    for (int mt = 0; mt < 4; mt++)
#pragma unroll
        for (int half = 0; half < 2; half++) {
            int chn = mbase + wm*64 + mt*16 + g + half*8;
            float bias = bt[chn];
            float s = 0.0f, qq = 0.0f;
#pragma unroll
            for (int nt = 0; nt < 2; nt++) {
                float v0 = acc[mt][nt][half*2]     + bias;
                float v1 = acc[mt][nt][half*2 + 1] + bias;
                int n = pixrow*32 + pixc0 + nt*8 + l4*2;
                *(float2*)&hbase[chn * SPI + sbase + n] = make_float2(v0, v1);
                s += v0 + v1;
                qq += v0*v0 + v1*v1;
            }
            s  += __shfl_xor_sync(0xffffffffu, s, 1);
            s  += __shfl_xor_sync(0xffffffffu, s, 2);
            qq += __shfl_xor_sync(0xffffffffu, qq, 1);
            qq += __shfl_xor_sync(0xffffffffu, qq, 2);
            if (l4 == 0) {
                atomicAdd(&g_bnsum[chn], s);
                atomicAdd(&g_bnsq[chn], qq);
            }
        }
}

// ---------------- conv2: double-buffered halo w/ BN+ReLU; residual -------------
__global__ __launch_bounds__(256) void conv2_gemm(const float* __restrict__ bt,
                                                  const float* __restrict__ bng, const float* __restrict__ bnb,
                                                  const float* __restrict__ gammas, int l) {
    __shared__ unsigned Hs[2][HTOT];
    __shared__ float s_scale[CCH];
    __shared__ float s_shift[CCH];
    int tid = threadIdx.x;
    int warp = tid >> 5, lane = tid & 31;
    int g = lane >> 2, l4 = lane & 3;
    int wm = warp & 1, wn = warp >> 1;
    int mbase = blockIdx.y * 128;
    int pbase = blockIdx.x * 64;
    int bimg = pbase >> 10, sbase = pbase & 1023;
    int r0 = sbase >> 5;
    const float* in0 = g_h + bimg * (CCH * SPI);
    const uint4* Ab = (const uint4*)((const unsigned*)g_q + C2_FRAG_OFF);
    int mtb = blockIdx.y * 8;
    int pixrow = wn >> 1, pixc0 = (wn & 1) * 16;
    int pixbase = pixrow*HROW + pixc0 + g;

    {
        float m = g_bnsum[tid] * (1.0f / (float)NPIX);
        float v = g_bnsq[tid] * (1.0f / (float)NPIX) - m * m;
        float sc = bng[tid] * rsqrtf(v + 1e-5f);
        s_scale[tid] = sc;
        s_shift[tid] = bnb[tid] - m * sc;
    }
    __syncthreads();

    int koffA[9], koffB[9];
#pragma unroll
    for (int ks = 0; ks < 9; ks++) {
        int k = ks*8 + l4;
        int cin = k / 9, jj = k - cin*9;
        koffA[ks] = cin*HCIN + (jj/3)*HROW + (jj%3);
        k += 4; cin = k / 9; jj = k - cin*9;
        koffB[ks] = cin*HCIN + (jj/3)*HROW + (jj%3);
    }

    int hoff[5];
#pragma unroll
    for (int it = 0; it < 5; it++) {
        int idx = tid + it*256;
        hoff[it] = -1;
        if (idx < HTOT) {
            int cin = idx / HCIN, rem = idx - cin*HCIN;
            int rr = rem / HROW, cc = rem - rr*HROW;
            int yy = r0 - 1 + rr, xx = cc - 1;
            if (yy >= 0 && yy < HH && xx >= 0 && xx < WWW)
                hoff[it] = cin*SPI + yy*WWW + xx;
        }
    }

    float acc[4][2][4];
#pragma unroll
    for (int mt = 0; mt < 4; mt++)
#pragma unroll
        for (int nt = 0; nt < 2; nt++)
#pragma unroll
            for (int r = 0; r < 4; r++) acc[mt][nt][r] = 0.0f;

    float pv[5];
#pragma unroll
    for (int it = 0; it < 5; it++) pv[it] = (hoff[it] >= 0) ? in0[hoff[it]] : 0.0f;
#pragma unroll
    for (int it = 0; it < 5; it++) {
        int idx = tid + it*256;
        if (idx < HTOT) {
            unsigned val = 0u;
            if (hoff[it] >= 0) {
                int c = hoff[it] >> 10;
                val = f2tf(fmaxf(pv[it] * s_scale[c] + s_shift[c], 0.0f));
            }
            Hs[0][idx] = val;
        }
    }
    {
        const float* nb = in0 + 8 * SPI;
#pragma unroll
        for (int it = 0; it < 5; it++) pv[it] = (hoff[it] >= 0) ? nb[hoff[it]] : 0.0f;
    }
    __syncthreads();

    for (int ch = 0; ch < 32; ch++) {
        if (ch + 1 < 32) {
#pragma unroll
            for (int it = 0; it < 5; it++) {
                int idx = tid + it*256;
                if (idx < HTOT) {
                    unsigned val = 0u;
                    if (hoff[it] >= 0) {
                        int c = (ch+1)*8 + (hoff[it] >> 10);
                        val = f2tf(fmaxf(pv[it] * s_scale[c] + s_shift[c], 0.0f));
                    }
                    Hs[(ch+1)&1][idx] = val;
                }
            }
            if (ch + 2 < 32) {
                const float* nb = in0 + (ch + 2) * 8 * SPI;
#pragma unroll
                for (int it = 0; it < 5; it++) pv[it] = (hoff[it] >= 0) ? nb[hoff[it]] : 0.0f;
            }
        }
        const unsigned* Hc = Hs[ch&1];
#pragma unroll
        for (int ks = 0; ks < 9; ks++) {
            int abase = ((ch*9 + ks)*16 + mtb + wm*4)*32 + lane;
            uint4 af[4];
#pragma unroll
            for (int mt = 0; mt < 4; mt++) af[mt] = Ab[abase + mt*32];
            unsigned b[2][2];
#pragma unroll
            for (int nt = 0; nt < 2; nt++) {
                b[nt][0] = Hc[koffA[ks] + pixbase + nt*8];
                b[nt][1] = Hc[koffB[ks] + pixbase + nt*8];
            }
#pragma unroll
            for (int mt = 0; mt < 4; mt++)
#pragma unroll
                for (int nt = 0; nt < 2; nt++)
                    mma8v(acc[mt][nt], af[mt], b[nt][0], b[nt][1]);
        }
        __syncthreads();
    }

    float gam = gammas[l];
    float* xbase = g_x + bimg * (CCH * SPI);
#pragma unroll
    for (int mt = 0; mt < 4; mt++)
#pragma unroll
        for (int half = 0; half < 2; half++) {
            int chn = mbase + wm*64 + mt*16 + g + half*8;
            float bias = bt[chn];
#pragma unroll
            for (int nt = 0; nt < 2; nt++) {
                int n = pixrow*32 + pixc0 + nt*8 + l4*2;
                float* dst = &xbase[chn * SPI + sbase + n];
                float2 old = *(float2*)dst;
                old.x += gam * (acc[mt][nt][half*2]     + bias);
                old.y += gam * (acc[mt][nt][half*2 + 1] + bias);
                *(float2*)dst = old;
            }
        }
}

// ---------------- launch ----------------
extern "C" void kernel_launch(void* const* d_in, const int* in_sizes, int n_in,
                              void* d_out, int out_size) {
    const float* x   = (const float*)d_in[0];
    const float* kw  = (const float*)d_in[1];
    const float* kb  = (const float*)d_in[2];
    const float* qw  = (const float*)d_in[3];
    const float* qb  = (const float*)d_in[4];
    const float* vw  = (const float*)d_in[5];
    const float* vb  = (const float*)d_in[6];
    const float* ow1 = (const float*)d_in[7];
    const float* ob1 = (const float*)d_in[8];
    const float* bng = (const float*)d_in[9];
    const float* bnb = (const float*)d_in[10];
    const float* ow2 = (const float*)d_in[11];
    const float* ob2 = (const float*)d_in[12];
    const float* gam = (const float*)d_in[13];

    copy_in<<<2048, 256>>>(x);
    for (int l = 0; l < NLAYERS; l++) {
        wconv_qkv<<<dim3(512, 3), 256>>>(kw + l*KHH*CCH, qw + l*KHH*CCH, vw + l*KHH*CCH);
        qkv_gemm<<<dim3(64, 12), 256>>>(kb + l*KHH, qb + l*KHH, vb + l*KHH, l);
        attn_kernel<<<8192, 256>>>(l);
        wconv<<<4608, 256>>>(ow1 + l*CCH*KHH*9, C1_FRAG_OFF, 4608, 72, 16);
        wconv<<<2304, 256>>>(ow2 + l*CCH*CCH*9, C2_FRAG_OFF, 2304, 72, 16);
        conv1_gemm<<<dim3(128, 2), 256>>>(ob1 + l*CCH);
        conv2_gemm<<<dim3(128, 2), 256>>>(ob2 + l*CCH, bng + l*CCH, bnb + l*CCH, gam, l);
    }
    copy_out<<<2048, 256>>>((float*)d_out);
}

// round 13
// speedup vs baseline: 1.0133x; 1.0133x over previous
#include <cuda_runtime.h>

#define NLAYERS 4
#define BATCH   8
#define CCH     256
#define HH      32
#define WWW     32
#define NHEADS  8
#define DHEAD   64
#define SPI     1024
#define NPIX    8192
#define NTOK    65536
#define KHH     512

// ---------------- scratch (green overlay set; no new globals) ----------------
__device__ __align__(16) float g_x[BATCH*CCH*SPI];
__device__ __align__(16) float g_keys[NLAYERS][NTOK*DHEAD];
__device__ __align__(16) float g_vals[NLAYERS][NTOK*DHEAD];
__device__ __align__(16) float g_q[NTOK*DHEAD];     // doubles as conv weight-frag scratch
__device__ __align__(16) float g_o[BATCH*KHH*SPI];
__device__ __align__(16) float g_h[BATCH*CCH*SPI];  // doubles as qkv weight-frag scratch
__device__ float g_bnsum[CCH];
__device__ float g_bnsq[CCH];

#define QKV_FRAG_SZ   131072
#define C1_FRAG_OFF   0
#define C2_FRAG_OFF   1179648

// halo geometry for 64-pixel (2-row) tiles: 4 rows x 34 cols per cin, 8 cins
#define HROW 34
#define HCIN 136
#define HTOT 1088

// ---------------- tf32 helpers ----------------
__device__ __forceinline__ unsigned f2tf(float x) {
    unsigned r;
    asm("cvt.rna.tf32.f32 %0, %1;" : "=r"(r) : "f"(x));
    return r;
}
__device__ __forceinline__ void mma8v(float (&d)[4], uint4 a, unsigned b0, unsigned b1) {
    asm volatile(
        "mma.sync.aligned.m16n8k8.row.col.f32.tf32.tf32.f32 "
        "{%0,%1,%2,%3}, {%4,%5,%6,%7}, {%8,%9}, {%0,%1,%2,%3};"
        : "+f"(d[0]), "+f"(d[1]), "+f"(d[2]), "+f"(d[3])
        : "r"(a.x), "r"(a.y), "r"(a.z), "r"(a.w), "r"(b0), "r"(b1));
}

// ---------------- weight conversion (qkv: one launch, grid.y selects matrix) ----
__global__ void wconv_qkv(const float* __restrict__ Wk, const float* __restrict__ Wq,
                          const float* __restrict__ Wv) {
    int type = blockIdx.y;
    const float* W = (type == 0) ? Wk : ((type == 1) ? Wq : Wv);
    unsigned* Wc = (unsigned*)g_h + type * QKV_FRAG_SZ;
    int idx = blockIdx.x * 256 + threadIdx.x;
    int m = idx >> 8, k = idx & 255;
    int ch = k >> 5, kc = k & 31;
    int ks = kc >> 3, c = kc & 7;
    int mt = m >> 4, rr = m & 15, gg = rr & 7;
    int lane = gg * 4 + (c & 3);
    int reg = (rr >> 3) + ((c >> 2) << 1);
    Wc[(((ch*4 + ks)*32 + mt)*32 + lane)*4 + reg] = f2tf(W[idx]);
}

__global__ void wconv(const float* __restrict__ W, int dstOff,
                      int Kdim, int CK, int NMT) {
    unsigned* Wc = (unsigned*)g_q + dstOff;
    int idx = blockIdx.x * 256 + threadIdx.x;
    int m = idx / Kdim, k = idx - m * Kdim;
    int ch = k / CK, kc = k - ch * CK;
    int ks = kc >> 3, c = kc & 7;
    int KS = CK >> 3;
    int mt = m >> 4, rr = m & 15, gg = rr & 7;
    int lane = gg * 4 + (c & 3);
    int reg = (rr >> 3) + ((c >> 2) << 1);
    Wc[(((ch*KS + ks)*NMT + mt)*32 + lane)*4 + reg] = f2tf(W[idx]);
}

// ---------------- copy in/out ----------------
__global__ void copy_in(const float* __restrict__ x) {
    int i = blockIdx.x * 256 + threadIdx.x;
    ((float4*)g_x)[i] = ((const float4*)x)[i];
}
__global__ void copy_out(float* __restrict__ out) {
    int i = blockIdx.x * 256 + threadIdx.x;
    ((float4*)out)[i] = ((const float4*)g_x)[i];
}

// ---------------- QKV 1x1 conv: R11 structure + af register pipeline ------------
__global__ __launch_bounds__(256) void qkv_gemm(
    const float* __restrict__ bk, const float* __restrict__ bq, const float* __restrict__ bv,
    int l)
{
    __shared__ unsigned Bs[32*136];
    int tid = threadIdx.x;
    int warp = tid >> 5, lane = tid & 31;
    int g = lane >> 2, l4 = lane & 3;
    int wm = warp & 1, wn = warp >> 1;
    int by = blockIdx.y, type = by >> 2, mb = by & 3;
    const float* bt = (type == 0) ? bk : ((type == 1) ? bq : bv);
    float* outb = (type == 0) ? g_keys[l] : ((type == 1) ? g_q : g_vals[l]);
    const uint4* Ab = (const uint4*)((const unsigned*)g_h + type * QKV_FRAG_SZ);

    int pbase = blockIdx.x * 128;
    int bimg = pbase >> 10, sbase = pbase & 1023;
    const float* xin = g_x + bimg * (CCH * SPI);

    float acc[4][4][4];
#pragma unroll
    for (int mt = 0; mt < 4; mt++)
#pragma unroll
        for (int nt = 0; nt < 4; nt++)
#pragma unroll
            for (int r = 0; r < 4; r++) acc[mt][nt][r] = 0.0f;

    int bcin = tid >> 3, bseg = (tid & 7) * 16;
    const float* bbase = xin + bcin * SPI + sbase + bseg;
    int awbase = (mb*8 + wm*4)*32 + lane;

    float4 pb[4];
    {
        const float4* bp = (const float4*)bbase;
#pragma unroll
        for (int j = 0; j < 4; j++) pb[j] = bp[j];
    }

    uint4 afb[2][4];

    for (int c = 0; c < 8; c++) {
#pragma unroll
        for (int j = 0; j < 4; j++) {
            float4 v = pb[j];
            uint4 u = make_uint4(f2tf(v.x), f2tf(v.y), f2tf(v.z), f2tf(v.w));
            *(uint4*)&Bs[bcin*136 + bseg + j*4] = u;
        }
        if (c + 1 < 8) {
            const float4* bp = (const float4*)(bbase + (c+1) * 32 * SPI);
#pragma unroll
            for (int j = 0; j < 4; j++) pb[j] = bp[j];
        }
        // preload af for ks=0 (global; latency hidden by the barrier)
        {
            int abase = (c*4)*1024 + awbase;
#pragma unroll
            for (int mt = 0; mt < 4; mt++) afb[0][mt] = Ab[abase + mt*32];
        }
        __syncthreads();
#pragma unroll
        for (int ks = 0; ks < 4; ks++) {
            if (ks + 1 < 4) {
                int abase = (c*4 + ks + 1)*1024 + awbase;
#pragma unroll
                for (int mt = 0; mt < 4; mt++) afb[(ks+1)&1][mt] = Ab[abase + mt*32];
            }
            unsigned b[4][2];
#pragma unroll
            for (int nt = 0; nt < 4; nt++) {
                int n = wn*32 + nt*8 + g;
                b[nt][0] = Bs[(ks*8 + l4)*136 + n];
                b[nt][1] = Bs[(ks*8 + l4 + 4)*136 + n];
            }
#pragma unroll
            for (int mt = 0; mt < 4; mt++)
#pragma unroll
                for (int nt = 0; nt < 4; nt++)
                    mma8v(acc[mt][nt], afb[ks&1][mt], b[nt][0], b[nt][1]);
        }
        __syncthreads();
    }

#pragma unroll
    for (int mt = 0; mt < 4; mt++)
#pragma unroll
        for (int half = 0; half < 2; half++) {
            int mg = mb*128 + wm*64 + mt*16 + g + half*8;
            float bias = bt[mg];
#pragma unroll
            for (int nt = 0; nt < 4; nt++) {
                int p = pbase + wn*32 + nt*8 + l4*2;
                outb[p*512 + mg]       = acc[mt][nt][half*2]     + bias;
                outb[(p+1)*512 + mg]   = acc[mt][nt][half*2 + 1] + bias;
            }
        }
}

// ---------------- attention (unchanged) ----------------
__global__ __launch_bounds__(256) void attn_kernel(int l) {
    if (blockIdx.x == 0) {
        g_bnsum[threadIdx.x] = 0.0f;
        g_bnsq[threadIdx.x] = 0.0f;
    }
    int warp = threadIdx.x >> 5, lane = threadIdx.x & 31;
    int tok = blockIdx.x * 8 + warp;

    float2 q = ((const float2*)&g_q[tok * DHEAD])[lane];
    q.x *= 0.125f; q.y *= 0.125f;

    float sc[5];
#pragma unroll 4
    for (int t = 0; t <= l; t++) {
        float2 kv = ((const float2*)&g_keys[t][tok * DHEAD])[lane];
        float p = q.x * kv.x + q.y * kv.y;
#pragma unroll
        for (int o = 16; o; o >>= 1) p += __shfl_xor_sync(0xffffffffu, p, o);
        sc[t] = p;
    }
    sc[l + 1] = 0.0f;
    int T = l + 2;

    float mx = sc[0];
    for (int t = 1; t < T; t++) mx = fmaxf(mx, sc[t]);
    float e[5], sum = 0.0f;
    for (int t = 0; t < T; t++) { e[t] = expf(sc[t] - mx); sum += e[t]; }
    float inv = 1.0f / sum;
    float a[5];
    for (int t = 0; t < T; t++) a[t] = e[t] * inv;

    if (T == 5) {
        float mn1 = fminf(fminf(a[0], a[1]), fminf(fminf(a[2], a[3]), a[4]));
        float mn2 = 1e30f; bool used = false;
        for (int t = 0; t < 5; t++) {
            if (!used && a[t] == mn1) used = true;
            else mn2 = fminf(mn2, a[t]);
        }
        float delta = mn2 + 1e-7f;
        float s2 = 0.0f;
        for (int t = 0; t < 5; t++) { a[t] = fmaxf(a[t] - delta, 0.0f); s2 += a[t]; }
        float r = 1.0f / (s2 + 1e-7f);
        for (int t = 0; t < 5; t++) a[t] *= r;
    }

    float2 oacc = make_float2(0.0f, 0.0f);
#pragma unroll 4
    for (int t = 0; t <= l; t++) {
        float2 vv = ((const float2*)&g_vals[t][tok * DHEAD])[lane];
        oacc.x += a[t] * vv.x;
        oacc.y += a[t] * vv.y;
    }

    int p = tok >> 3, head = tok & 7;
    int bimg = p >> 10, s = p & 1023;
    float* op = g_o + bimg * (KHH * SPI) + (head * DHEAD + lane * 2) * SPI + s;
    op[0]   = oacc.x;
    op[SPI] = oacc.y;
}

// ---------------- conv1: R11 structure + af register pipeline -------------------
__global__ __launch_bounds__(256) void conv1_gemm(const float* __restrict__ bt) {
    __shared__ unsigned Hs[HTOT];
    int tid = threadIdx.x;
    int warp = tid >> 5, lane = tid & 31;
    int g = lane >> 2, l4 = lane & 3;
    int wm = warp & 1, wn = warp >> 1;
    int mbase = blockIdx.y * 128;
    int pbase = blockIdx.x * 64;
    int bimg = pbase >> 10, sbase = pbase & 1023;
    int r0 = sbase >> 5;
    const float* in0 = g_o + bimg * (KHH * SPI);
    const uint4* Ab = (const uint4*)((const unsigned*)g_q + C1_FRAG_OFF);
    int mtb = blockIdx.y * 8;
    int pixrow = wn >> 1, pixc0 = (wn & 1) * 16;
    int pixbase = pixrow*HROW + pixc0 + g;
    int awbase = (mtb + wm*4)*32 + lane;

    int koffA[9], koffB[9];
#pragma unroll
    for (int ks = 0; ks < 9; ks++) {
        int k = ks*8 + l4;
        int cin = k / 9, jj = k - cin*9;
        koffA[ks] = cin*HCIN + (jj/3)*HROW + (jj%3);
        k += 4; cin = k / 9; jj = k - cin*9;
        koffB[ks] = cin*HCIN + (jj/3)*HROW + (jj%3);
    }

    int hoff[5];
#pragma unroll
    for (int it = 0; it < 5; it++) {
        int idx = tid + it*256;
        hoff[it] = -1;
        if (idx < HTOT) {
            int cin = idx / HCIN, rem = idx - cin*HCIN;
            int rr = rem / HROW, cc = rem - rr*HROW;
            int yy = r0 - 1 + rr, xx = cc - 1;
            if (yy >= 0 && yy < HH && xx >= 0 && xx < WWW)
                hoff[it] = cin*SPI + yy*WWW + xx;
        }
    }

    float acc[4][2][4];
#pragma unroll
    for (int mt = 0; mt < 4; mt++)
#pragma unroll
        for (int nt = 0; nt < 2; nt++)
#pragma unroll
            for (int r = 0; r < 4; r++) acc[mt][nt][r] = 0.0f;

    float pv[5];
#pragma unroll
    for (int it = 0; it < 5; it++) pv[it] = (hoff[it] >= 0) ? in0[hoff[it]] : 0.0f;

    uint4 afb[2][4];

    for (int ch = 0; ch < 64; ch++) {
#pragma unroll
        for (int it = 0; it < 5; it++) {
            int idx = tid + it*256;
            if (idx < HTOT) Hs[idx] = f2tf(pv[it]);
        }
        if (ch + 1 < 64) {
            const float* nb = in0 + (ch + 1) * 8 * SPI;
#pragma unroll
            for (int it = 0; it < 5; it++) pv[it] = (hoff[it] >= 0) ? nb[hoff[it]] : 0.0f;
        }
        // preload af for ks=0 (hidden by barrier)
        {
            int abase = (ch*9)*512 + awbase;
#pragma unroll
            for (int mt = 0; mt < 4; mt++) afb[0][mt] = Ab[abase + mt*32];
        }
        __syncthreads();
#pragma unroll
        for (int ks = 0; ks < 9; ks++) {
            if (ks + 1 < 9) {
                int abase = (ch*9 + ks + 1)*512 + awbase;
#pragma unroll
                for (int mt = 0; mt < 4; mt++) afb[(ks+1)&1][mt] = Ab[abase + mt*32];
            }
            unsigned b[2][2];
#pragma unroll
            for (int nt = 0; nt < 2; nt++) {
                b[nt][0] = Hs[koffA[ks] + pixbase + nt*8];
                b[nt][1] = Hs[koffB[ks] + pixbase + nt*8];
            }
#pragma unroll
            for (int mt = 0; mt < 4; mt++)
#pragma unroll
                for (int nt = 0; nt < 2; nt++)
                    mma8v(acc[mt][nt], afb[ks&1][mt], b[nt][0], b[nt][1]);
        }
        __syncthreads();
    }

    float* hbase = g_h + bimg * (CCH * SPI);
#pragma unroll
    for (int mt = 0; mt < 4; mt++)
#pragma unroll
        for (int half = 0; half < 2; half++) {
            int chn = mbase + wm*64 + mt*16 + g + half*8;
            float bias = bt[chn];
            float s = 0.0f, qq = 0.0f;
#pragma unroll
            for (int nt = 0; nt < 2; nt++) {
                float v0 = acc[mt][nt][half*2]     + bias;
                float v1 = acc[mt][nt][half*2 + 1] + bias;
                int n = pixrow*32 + pixc0 + nt*8 + l4*2;
                *(float2*)&hbase[chn * SPI + sbase + n] = make_float2(v0, v1);
                s += v0 + v1;
                qq += v0*v0 + v1*v1;
            }
            s  += __shfl_xor_sync(0xffffffffu, s, 1);
            s  += __shfl_xor_sync(0xffffffffu, s, 2);
            qq += __shfl_xor_sync(0xffffffffu, qq, 1);
            qq += __shfl_xor_sync(0xffffffffu, qq, 2);
            if (l4 == 0) {
                atomicAdd(&g_bnsum[chn], s);
                atomicAdd(&g_bnsq[chn], qq);
            }
        }
}

// ---------------- conv2: R11 structure + af register pipeline -------------------
__global__ __launch_bounds__(256) void conv2_gemm(const float* __restrict__ bt,
                                                  const float* __restrict__ bng, const float* __restrict__ bnb,
                                                  const float* __restrict__ gammas, int l) {
    __shared__ unsigned Hs[HTOT];
    __shared__ float s_scale[CCH];
    __shared__ float s_shift[CCH];
    int tid = threadIdx.x;
    int warp = tid >> 5, lane = tid & 31;
    int g = lane >> 2, l4 = lane & 3;
    int wm = warp & 1, wn = warp >> 1;
    int mbase = blockIdx.y * 128;
    int pbase = blockIdx.x * 64;
    int bimg = pbase >> 10, sbase = pbase & 1023;
    int r0 = sbase >> 5;
    const float* in0 = g_h + bimg * (CCH * SPI);
    const uint4* Ab = (const uint4*)((const unsigned*)g_q + C2_FRAG_OFF);
    int mtb = blockIdx.y * 8;
    int pixrow = wn >> 1, pixc0 = (wn & 1) * 16;
    int pixbase = pixrow*HROW + pixc0 + g;
    int awbase = (mtb + wm*4)*32 + lane;

    {
        float m = g_bnsum[tid] * (1.0f / (float)NPIX);
        float v = g_bnsq[tid] * (1.0f / (float)NPIX) - m * m;
        float sc = bng[tid] * rsqrtf(v + 1e-5f);
        s_scale[tid] = sc;
        s_shift[tid] = bnb[tid] - m * sc;
    }
    __syncthreads();

    int koffA[9], koffB[9];
#pragma unroll
    for (int ks = 0; ks < 9; ks++) {
        int k = ks*8 + l4;
        int cin = k / 9, jj = k - cin*9;
        koffA[ks] = cin*HCIN + (jj/3)*HROW + (jj%3);
        k += 4; cin = k / 9; jj = k - cin*9;
        koffB[ks] = cin*HCIN + (jj/3)*HROW + (jj%3);
    }

    int hoff[5];
#pragma unroll
    for (int it = 0; it < 5; it++) {
        int idx = tid + it*256;
        hoff[it] = -1;
        if (idx < HTOT) {
            int cin = idx / HCIN, rem = idx - cin*HCIN;
            int rr = rem / HROW, cc = rem - rr*HROW;
            int yy = r0 - 1 + rr, xx = cc - 1;
            if (yy >= 0 && yy < HH && xx >= 0 && xx < WWW)
                hoff[it] = cin*SPI + yy*WWW + xx;
        }
    }

    float acc[4][2][4];
#pragma unroll
    for (int mt = 0; mt < 4; mt++)
#pragma unroll
        for (int nt = 0; nt < 2; nt++)
#pragma unroll
            for (int r = 0; r < 4; r++) acc[mt][nt][r] = 0.0f;

    float pv[5];
#pragma unroll
    for (int it = 0; it < 5; it++) pv[it] = (hoff[it] >= 0) ? in0[hoff[it]] : 0.0f;

    uint4 afb[2][4];

    for (int ch = 0; ch < 32; ch++) {
#pragma unroll
        for (int it = 0; it < 5; it++) {
            int idx = tid + it*256;
            if (idx < HTOT) {
                unsigned val = 0u;
                if (hoff[it] >= 0) {
                    int c = ch*8 + (hoff[it] >> 10);
                    val = f2tf(fmaxf(pv[it] * s_scale[c] + s_shift[c], 0.0f));
                }
                Hs[idx] = val;
            }
        }
        if (ch + 1 < 32) {
            const float* nb = in0 + (ch + 1) * 8 * SPI;
#pragma unroll
            for (int it = 0; it < 5; it++) pv[it] = (hoff[it] >= 0) ? nb[hoff[it]] : 0.0f;
        }
        {
            int abase = (ch*9)*512 + awbase;
#pragma unroll
            for (int mt = 0; mt < 4; mt++) afb[0][mt] = Ab[abase + mt*32];
        }
        __syncthreads();
#pragma unroll
        for (int ks = 0; ks < 9; ks++) {
            if (ks + 1 < 9) {
                int abase = (ch*9 + ks + 1)*512 + awbase;
#pragma unroll
                for (int mt = 0; mt < 4; mt++) afb[(ks+1)&1][mt] = Ab[abase + mt*32];
            }
            unsigned b[2][2];
#pragma unroll
            for (int nt = 0; nt < 2; nt++) {
                b[nt][0] = Hs[koffA[ks] + pixbase + nt*8];
                b[nt][1] = Hs[koffB[ks] + pixbase + nt*8];
            }
#pragma unroll
            for (int mt = 0; mt < 4; mt++)
#pragma unroll
                for (int nt = 0; nt < 2; nt++)
                    mma8v(acc[mt][nt], afb[ks&1][mt], b[nt][0], b[nt][1]);
        }
        __syncthreads();
    }

    float gam = gammas[l];
    float* xbase = g_x + bimg * (CCH * SPI);
#pragma unroll
    for (int mt = 0; mt < 4; mt++)
#pragma unroll
        for (int half = 0; half < 2; half++) {
            int chn = mbase + wm*64 + mt*16 + g + half*8;
            float bias = bt[chn];
#pragma unroll
            for (int nt = 0; nt < 2; nt++) {
                int n = pixrow*32 + pixc0 + nt*8 + l4*2;
                float* dst = &xbase[chn * SPI + sbase + n];
                float2 old = *(float2*)dst;
                old.x += gam * (acc[mt][nt][half*2]     + bias);
                old.y += gam * (acc[mt][nt][half*2 + 1] + bias);
                *(float2*)dst = old;
            }
        }
}

// ---------------- launch ----------------
extern "C" void kernel_launch(void* const* d_in, const int* in_sizes, int n_in,
                              void* d_out, int out_size) {
    const float* x   = (const float*)d_in[0];
    const float* kw  = (const float*)d_in[1];
    const float* kb  = (const float*)d_in[2];
    const float* qw  = (const float*)d_in[3];
    const float* qb  = (const float*)d_in[4];
    const float* vw  = (const float*)d_in[5];
    const float* vb  = (const float*)d_in[6];
    const float* ow1 = (const float*)d_in[7];
    const float* ob1 = (const float*)d_in[8];
    const float* bng = (const float*)d_in[9];
    const float* bnb = (const float*)d_in[10];
    const float* ow2 = (const float*)d_in[11];
    const float* ob2 = (const float*)d_in[12];
    const float* gam = (const float*)d_in[13];

    copy_in<<<2048, 256>>>(x);
    for (int l = 0; l < NLAYERS; l++) {
        wconv_qkv<<<dim3(512, 3), 256>>>(kw + l*KHH*CCH, qw + l*KHH*CCH, vw + l*KHH*CCH);
        qkv_gemm<<<dim3(64, 12), 256>>>(kb + l*KHH, qb + l*KHH, vb + l*KHH, l);
        attn_kernel<<<8192, 256>>>(l);
        wconv<<<4608, 256>>>(ow1 + l*CCH*KHH*9, C1_FRAG_OFF, 4608, 72, 16);
        wconv<<<2304, 256>>>(ow2 + l*CCH*CCH*9, C2_FRAG_OFF, 2304, 72, 16);
        conv1_gemm<<<dim3(128, 2), 256>>>(ob1 + l*CCH);
        conv2_gemm<<<dim3(128, 2), 256>>>(ob2 + l*CCH, bng + l*CCH, bnb + l*CCH, gam, l);
    }
    copy_out<<<2048, 256>>>((float*)d_out);
}

// round 14
// speedup vs baseline: 1.1485x; 1.1335x over previous
#include <cuda_runtime.h>

#define NLAYERS 4
#define BATCH   8
#define CCH     256
#define HH      32
#define WWW     32
#define NHEADS  8
#define DHEAD   64
#define SPI     1024
#define NPIX    8192
#define NTOK    65536
#define KHH     512

// ---------------- scratch (green overlay set; no new globals) ----------------
__device__ __align__(16) float g_x[BATCH*CCH*SPI];
__device__ __align__(16) float g_keys[NLAYERS][NTOK*DHEAD];
__device__ __align__(16) float g_vals[NLAYERS][NTOK*DHEAD];
__device__ __align__(16) float g_q[NTOK*DHEAD];     // doubles as conv weight-frag scratch
__device__ __align__(16) float g_o[BATCH*KHH*SPI];
__device__ __align__(16) float g_h[BATCH*CCH*SPI];  // doubles as qkv weight-frag scratch
__device__ float g_bnsum[CCH];
__device__ float g_bnsq[CCH];

#define QKV_FRAG_SZ   131072
#define C1_FRAG_OFF   0
#define C2_FRAG_OFF   1179648

// halo geometry for 64-pixel (2-row) tiles
#define HROW 34
#define HCIN 136
#define HTOT 1088

// ---------------- tf32 helpers ----------------
__device__ __forceinline__ unsigned f2tf(float x) {
    unsigned r;
    asm("cvt.rna.tf32.f32 %0, %1;" : "=r"(r) : "f"(x));
    return r;
}
__device__ __forceinline__ void mma8v(float (&d)[4], uint4 a, unsigned b0, unsigned b1) {
    asm volatile(
        "mma.sync.aligned.m16n8k8.row.col.f32.tf32.tf32.f32 "
        "{%0,%1,%2,%3}, {%4,%5,%6,%7}, {%8,%9}, {%0,%1,%2,%3};"
        : "+f"(d[0]), "+f"(d[1]), "+f"(d[2]), "+f"(d[3])
        : "r"(a.x), "r"(a.y), "r"(a.z), "r"(a.w), "r"(b0), "r"(b1));
}

// ---------------- weight conversion: qkv (one launch) ----------------
__global__ void wconv_qkv(const float* __restrict__ Wk, const float* __restrict__ Wq,
                          const float* __restrict__ Wv) {
    int type = blockIdx.y;
    const float* W = (type == 0) ? Wk : ((type == 1) ? Wq : Wv);
    unsigned* Wc = (unsigned*)g_h + type * QKV_FRAG_SZ;
    int idx = blockIdx.x * 256 + threadIdx.x;
    int m = idx >> 8, k = idx & 255;
    int ch = k >> 5, kc = k & 31;
    int ks = kc >> 3, c = kc & 7;
    int mt = m >> 4, rr = m & 15, gg = rr & 7;
    int lane = gg * 4 + (c & 3);
    int reg = (rr >> 3) + ((c >> 2) << 1);
    Wc[(((ch*4 + ks)*32 + mt)*32 + lane)*4 + reg] = f2tf(W[idx]);
}

// ---------------- weight conversion: both convs in one launch ----------------
__global__ void wconv_c12(const float* __restrict__ W1, const float* __restrict__ W2) {
    int b = blockIdx.x;
    const float* W;
    unsigned* Wc;
    int Kdim, idx;
    if (b < 4608) {
        W = W1; Wc = (unsigned*)g_q + C1_FRAG_OFF; Kdim = 4608;
        idx = b * 256 + threadIdx.x;
    } else {
        W = W2; Wc = (unsigned*)g_q + C2_FRAG_OFF; Kdim = 2304;
        idx = (b - 4608) * 256 + threadIdx.x;
    }
    int m = idx / Kdim, k = idx - m * Kdim;
    int ch = k / 72, kc = k - ch * 72;
    int ks = kc >> 3, c = kc & 7;
    int mt = m >> 4, rr = m & 15, gg = rr & 7;
    int lane = gg * 4 + (c & 3);
    int reg = (rr >> 3) + ((c >> 2) << 1);
    Wc[(((ch*9 + ks)*16 + mt)*32 + lane)*4 + reg] = f2tf(W[idx]);
}

// ---------------- copy in/out ----------------
__global__ void copy_in(const float* __restrict__ x) {
    int i = blockIdx.x * 256 + threadIdx.x;
    ((float4*)g_x)[i] = ((const float4*)x)[i];
}
__global__ void copy_out(float* __restrict__ out) {
    int i = blockIdx.x * 256 + threadIdx.x;
    ((float4*)out)[i] = ((const float4*)g_x)[i];
}

// ---------------- QKV 1x1 conv: R11 mainloop + coalesced smem-transpose epilogue
__global__ __launch_bounds__(256) void qkv_gemm(
    const float* __restrict__ bk, const float* __restrict__ bq, const float* __restrict__ bv,
    int l)
{
    __shared__ unsigned Bs[32*136];
    int tid = threadIdx.x;
    int warp = tid >> 5, lane = tid & 31;
    int g = lane >> 2, l4 = lane & 3;
    int wm = warp & 1, wn = warp >> 1;
    int by = blockIdx.y, type = by >> 2, mb = by & 3;
    const float* bt = (type == 0) ? bk : ((type == 1) ? bq : bv);
    float* outb = (type == 0) ? g_keys[l] : ((type == 1) ? g_q : g_vals[l]);
    const uint4* Ab = (const uint4*)((const unsigned*)g_h + type * QKV_FRAG_SZ);

    int pbase = blockIdx.x * 128;
    int bimg = pbase >> 10, sbase = pbase & 1023;
    const float* xin = g_x + bimg * (CCH * SPI);

    float acc[4][4][4];
#pragma unroll
    for (int mt = 0; mt < 4; mt++)
#pragma unroll
        for (int nt = 0; nt < 4; nt++)
#pragma unroll
            for (int r = 0; r < 4; r++) acc[mt][nt][r] = 0.0f;

    int bcin = tid >> 3, bseg = (tid & 7) * 16;
    const float* bbase = xin + bcin * SPI + sbase + bseg;

    float4 pb[4];
    {
        const float4* bp = (const float4*)bbase;
#pragma unroll
        for (int j = 0; j < 4; j++) pb[j] = bp[j];
    }

    for (int c = 0; c < 8; c++) {
#pragma unroll
        for (int j = 0; j < 4; j++) {
            float4 v = pb[j];
            uint4 u = make_uint4(f2tf(v.x), f2tf(v.y), f2tf(v.z), f2tf(v.w));
            *(uint4*)&Bs[bcin*136 + bseg + j*4] = u;
        }
        if (c + 1 < 8) {
            const float4* bp = (const float4*)(bbase + (c+1) * 32 * SPI);
#pragma unroll
            for (int j = 0; j < 4; j++) pb[j] = bp[j];
        }
        __syncthreads();
#pragma unroll
        for (int ks = 0; ks < 4; ks++) {
            int abase = ((c*4 + ks)*32 + mb*8 + wm*4)*32 + lane;
            uint4 af[4];
#pragma unroll
            for (int mt = 0; mt < 4; mt++) af[mt] = Ab[abase + mt*32];
            unsigned b[4][2];
#pragma unroll
            for (int nt = 0; nt < 4; nt++) {
                int n = wn*32 + nt*8 + g;
                b[nt][0] = Bs[(ks*8 + l4)*136 + n];
                b[nt][1] = Bs[(ks*8 + l4 + 4)*136 + n];
            }
#pragma unroll
            for (int mt = 0; mt < 4; mt++)
#pragma unroll
                for (int nt = 0; nt < 4; nt++)
                    mma8v(acc[mt][nt], af[mt], b[nt][0], b[nt][1]);
        }
        __syncthreads();
    }

    // epilogue: 4 chunks (one per wn quarter), smem transpose -> coalesced stores
    float* S = (float*)Bs;   // [32][129]
#pragma unroll
    for (int qn = 0; qn < 4; qn++) {
        if (wn == qn) {
#pragma unroll
            for (int mt = 0; mt < 4; mt++)
#pragma unroll
                for (int r2 = 0; r2 < 2; r2++) {
                    int mgl = wm*64 + mt*16 + g + r2*8;
                    float bias = bt[mb*128 + mgl];
#pragma unroll
                    for (int nt = 0; nt < 4; nt++) {
                        int pl = nt*8 + l4*2;
                        S[pl*129 + mgl]       = acc[mt][nt][r2*2]     + bias;
                        S[(pl+1)*129 + mgl]   = acc[mt][nt][r2*2 + 1] + bias;
                    }
                }
        }
        __syncthreads();
        {
            int pl = tid >> 3, grp = tid & 7;
            float* dst = outb + (pbase + qn*32 + pl) * 512 + mb*128;
            const float* src = &S[pl*129];
#pragma unroll
            for (int j = 0; j < 4; j++) {
                int o = j*32 + grp*4;
                *(float4*)(dst + o) = make_float4(src[o], src[o+1], src[o+2], src[o+3]);
            }
        }
        __syncthreads();
    }
}

// ---------------- attention (unchanged) ----------------
__global__ __launch_bounds__(256) void attn_kernel(int l) {
    if (blockIdx.x == 0) {
        g_bnsum[threadIdx.x] = 0.0f;
        g_bnsq[threadIdx.x] = 0.0f;
    }
    int warp = threadIdx.x >> 5, lane = threadIdx.x & 31;
    int tok = blockIdx.x * 8 + warp;

    float2 q = ((const float2*)&g_q[tok * DHEAD])[lane];
    q.x *= 0.125f; q.y *= 0.125f;

    float sc[5];
#pragma unroll 4
    for (int t = 0; t <= l; t++) {
        float2 kv = ((const float2*)&g_keys[t][tok * DHEAD])[lane];
        float p = q.x * kv.x + q.y * kv.y;
#pragma unroll
        for (int o = 16; o; o >>= 1) p += __shfl_xor_sync(0xffffffffu, p, o);
        sc[t] = p;
    }
    sc[l + 1] = 0.0f;
    int T = l + 2;

    float mx = sc[0];
    for (int t = 1; t < T; t++) mx = fmaxf(mx, sc[t]);
    float e[5], sum = 0.0f;
    for (int t = 0; t < T; t++) { e[t] = expf(sc[t] - mx); sum += e[t]; }
    float inv = 1.0f / sum;
    float a[5];
    for (int t = 0; t < T; t++) a[t] = e[t] * inv;

    if (T == 5) {
        float mn1 = fminf(fminf(a[0], a[1]), fminf(fminf(a[2], a[3]), a[4]));
        float mn2 = 1e30f; bool used = false;
        for (int t = 0; t < 5; t++) {
            if (!used && a[t] == mn1) used = true;
            else mn2 = fminf(mn2, a[t]);
        }
        float delta = mn2 + 1e-7f;
        float s2 = 0.0f;
        for (int t = 0; t < 5; t++) { a[t] = fmaxf(a[t] - delta, 0.0f); s2 += a[t]; }
        float r = 1.0f / (s2 + 1e-7f);
        for (int t = 0; t < 5; t++) a[t] *= r;
    }

    float2 oacc = make_float2(0.0f, 0.0f);
#pragma unroll 4
    for (int t = 0; t <= l; t++) {
        float2 vv = ((const float2*)&g_vals[t][tok * DHEAD])[lane];
        oacc.x += a[t] * vv.x;
        oacc.y += a[t] * vv.y;
    }

    int p = tok >> 3, head = tok & 7;
    int bimg = p >> 10, s = p & 1023;
    float* op = g_o + bimg * (KHH * SPI) + (head * DHEAD + lane * 2) * SPI + s;
    op[0]   = oacc.x;
    op[SPI] = oacc.y;
}

// ---------------- conv1: byte-exact R11 structure ----------------
__global__ __launch_bounds__(256) void conv1_gemm(const float* __restrict__ bt) {
    __shared__ unsigned Hs[HTOT];
    int tid = threadIdx.x;
    int warp = tid >> 5, lane = tid & 31;
    int g = lane >> 2, l4 = lane & 3;
    int wm = warp & 1, wn = warp >> 1;
    int mbase = blockIdx.y * 128;
    int pbase = blockIdx.x * 64;
    int bimg = pbase >> 10, sbase = pbase & 1023;
    int r0 = sbase >> 5;
    const float* in0 = g_o + bimg * (KHH * SPI);
    const uint4* Ab = (const uint4*)((const unsigned*)g_q + C1_FRAG_OFF);
    int mtb = blockIdx.y * 8;
    int pixrow = wn >> 1, pixc0 = (wn & 1) * 16;
    int pixbase = pixrow*HROW + pixc0 + g;

    int koffA[9], koffB[9];
#pragma unroll
    for (int ks = 0; ks < 9; ks++) {
        int k = ks*8 + l4;
        int cin = k / 9, jj = k - cin*9;
        koffA[ks] = cin*HCIN + (jj/3)*HROW + (jj%3);
        k += 4; cin = k / 9; jj = k - cin*9;
        koffB[ks] = cin*HCIN + (jj/3)*HROW + (jj%3);
    }

    int hoff[5];
#pragma unroll
    for (int it = 0; it < 5; it++) {
        int idx = tid + it*256;
        hoff[it] = -1;
        if (idx < HTOT) {
            int cin = idx / HCIN, rem = idx - cin*HCIN;
            int rr = rem / HROW, cc = rem - rr*HROW;
            int yy = r0 - 1 + rr, xx = cc - 1;
            if (yy >= 0 && yy < HH && xx >= 0 && xx < WWW)
                hoff[it] = cin*SPI + yy*WWW + xx;
        }
    }

    float acc[4][2][4];
#pragma unroll
    for (int mt = 0; mt < 4; mt++)
#pragma unroll
        for (int nt = 0; nt < 2; nt++)
#pragma unroll
            for (int r = 0; r < 4; r++) acc[mt][nt][r] = 0.0f;

    float pv[5];
#pragma unroll
    for (int it = 0; it < 5; it++) pv[it] = (hoff[it] >= 0) ? in0[hoff[it]] : 0.0f;

    for (int ch = 0; ch < 64; ch++) {
#pragma unroll
        for (int it = 0; it < 5; it++) {
            int idx = tid + it*256;
            if (idx < HTOT) Hs[idx] = f2tf(pv[it]);
        }
        if (ch + 1 < 64) {
            const float* nb = in0 + (ch + 1) * 8 * SPI;
#pragma unroll
            for (int it = 0; it < 5; it++) pv[it] = (hoff[it] >= 0) ? nb[hoff[it]] : 0.0f;
        }
        __syncthreads();
#pragma unroll
        for (int ks = 0; ks < 9; ks++) {
            int abase = ((ch*9 + ks)*16 + mtb + wm*4)*32 + lane;
            uint4 af[4];
#pragma unroll
            for (int mt = 0; mt < 4; mt++) af[mt] = Ab[abase + mt*32];
            unsigned b[2][2];
#pragma unroll
            for (int nt = 0; nt < 2; nt++) {
                b[nt][0] = Hs[koffA[ks] + pixbase + nt*8];
                b[nt][1] = Hs[koffB[ks] + pixbase + nt*8];
            }
#pragma unroll
            for (int mt = 0; mt < 4; mt++)
#pragma unroll
                for (int nt = 0; nt < 2; nt++)
                    mma8v(acc[mt][nt], af[mt], b[nt][0], b[nt][1]);
        }
        __syncthreads();
    }

    float* hbase = g_h + bimg * (CCH * SPI);
#pragma unroll
    for (int mt = 0; mt < 4; mt++)
#pragma unroll
        for (int half = 0; half < 2; half++) {
            int chn = mbase + wm*64 + mt*16 + g + half*8;
            float bias = bt[chn];
            float s = 0.0f, qq = 0.0f;
#pragma unroll
            for (int nt = 0; nt < 2; nt++) {
                float v0 = acc[mt][nt][half*2]     + bias;
                float v1 = acc[mt][nt][half*2 + 1] + bias;
                int n = pixrow*32 + pixc0 + nt*8 + l4*2;
                *(float2*)&hbase[chn * SPI + sbase + n] = make_float2(v0, v1);
                s += v0 + v1;
                qq += v0*v0 + v1*v1;
            }
            s  += __shfl_xor_sync(0xffffffffu, s, 1);
            s  += __shfl_xor_sync(0xffffffffu, s, 2);
            qq += __shfl_xor_sync(0xffffffffu, qq, 1);
            qq += __shfl_xor_sync(0xffffffffu, qq, 2);
            if (l4 == 0) {
                atomicAdd(&g_bnsum[chn], s);
                atomicAdd(&g_bnsq[chn], qq);
            }
        }
}

// ---------------- conv2: byte-exact R11 structure ----------------
__global__ __launch_bounds__(256) void conv2_gemm(const float* __restrict__ bt,
                                                  const float* __restrict__ bng, const float* __restrict__ bnb,
                                                  const float* __restrict__ gammas, int l) {
    __shared__ unsigned Hs[HTOT];
    __shared__ float s_scale[CCH];
    __shared__ float s_shift[CCH];
    int tid = threadIdx.x;
    int warp = tid >> 5, lane = tid & 31;
    int g = lane >> 2, l4 = lane & 3;
    int wm = warp & 1, wn = warp >> 1;
    int mbase = blockIdx.y * 128;
    int pbase = blockIdx.x * 64;
    int bimg = pbase >> 10, sbase = pbase & 1023;
    int r0 = sbase >> 5;
    const float* in0 = g_h + bimg * (CCH * SPI);
    const uint4* Ab = (const uint4*)((const unsigned*)g_q + C2_FRAG_OFF);
    int mtb = blockIdx.y * 8;
    int pixrow = wn >> 1, pixc0 = (wn & 1) * 16;
    int pixbase = pixrow*HROW + pixc0 + g;

    {
        float m = g_bnsum[tid] * (1.0f / (float)NPIX);
        float v = g_bnsq[tid] * (1.0f / (float)NPIX) - m * m;
        float sc = bng[tid] * rsqrtf(v + 1e-5f);
        s_scale[tid] = sc;
        s_shift[tid] = bnb[tid] - m * sc;
    }
    __syncthreads();

    int koffA[9], koffB[9];
#pragma unroll
    for (int ks = 0; ks < 9; ks++) {
        int k = ks*8 + l4;
        int cin = k / 9, jj = k - cin*9;
        koffA[ks] = cin*HCIN + (jj/3)*HROW + (jj%3);
        k += 4; cin = k / 9; jj = k - cin*9;
        koffB[ks] = cin*HCIN + (jj/3)*HROW + (jj%3);
    }

    int hoff[5];
#pragma unroll
    for (int it = 0; it < 5; it++) {
        int idx = tid + it*256;
        hoff[it] = -1;
        if (idx < HTOT) {
            int cin = idx / HCIN, rem = idx - cin*HCIN;
            int rr = rem / HROW, cc = rem - rr*HROW;
            int yy = r0 - 1 + rr, xx = cc - 1;
            if (yy >= 0 && yy < HH && xx >= 0 && xx < WWW)
                hoff[it] = cin*SPI + yy*WWW + xx;
        }
    }

    float acc[4][2][4];
#pragma unroll
    for (int mt = 0; mt < 4; mt++)
#pragma unroll
        for (int nt = 0; nt < 2; nt++)
#pragma unroll
            for (int r = 0; r < 4; r++) acc[mt][nt][r] = 0.0f;

    float pv[5];
#pragma unroll
    for (int it = 0; it < 5; it++) pv[it] = (hoff[it] >= 0) ? in0[hoff[it]] : 0.0f;

    for (int ch = 0; ch < 32; ch++) {
#pragma unroll
        for (int it = 0; it < 5; it++) {
            int idx = tid + it*256;
            if (idx < HTOT) {
                unsigned val = 0u;
                if (hoff[it] >= 0) {
                    int c = ch*8 + (hoff[it] >> 10);
                    val = f2tf(fmaxf(pv[it] * s_scale[c] + s_shift[c], 0.0f));
                }
                Hs[idx] = val;
            }
        }
        if (ch + 1 < 32) {
            const float* nb = in0 + (ch + 1) * 8 * SPI;
#pragma unroll
            for (int it = 0; it < 5; it++) pv[it] = (hoff[it] >= 0) ? nb[hoff[it]] : 0.0f;
        }
        __syncthreads();
#pragma unroll
        for (int ks = 0; ks < 9; ks++) {
            int abase = ((ch*9 + ks)*16 + mtb + wm*4)*32 + lane;
            uint4 af[4];
#pragma unroll
            for (int mt = 0; mt < 4; mt++) af[mt] = Ab[abase + mt*32];
            unsigned b[2][2];
#pragma unroll
            for (int nt = 0; nt < 2; nt++) {
                b[nt][0] = Hs[koffA[ks] + pixbase + nt*8];
                b[nt][1] = Hs[koffB[ks] + pixbase + nt*8];
            }
#pragma unroll
            for (int mt = 0; mt < 4; mt++)
#pragma unroll
                for (int nt = 0; nt < 2; nt++)
                    mma8v(acc[mt][nt], af[mt], b[nt][0], b[nt][1]);
        }
        __syncthreads();
    }

    float gam = gammas[l];
    float* xbase = g_x + bimg * (CCH * SPI);
#pragma unroll
    for (int mt = 0; mt < 4; mt++)
#pragma unroll
        for (int half = 0; half < 2; half++) {
            int chn = mbase + wm*64 + mt*16 + g + half*8;
            float bias = bt[chn];
#pragma unroll
            for (int nt = 0; nt < 2; nt++) {
                int n = pixrow*32 + pixc0 + nt*8 + l4*2;
                float* dst = &xbase[chn * SPI + sbase + n];
                float2 old = *(float2*)dst;
                old.x += gam * (acc[mt][nt][half*2]     + bias);
                old.y += gam * (acc[mt][nt][half*2 + 1] + bias);
                *(float2*)dst = old;
            }
        }
}

// ---------------- launch ----------------
extern "C" void kernel_launch(void* const* d_in, const int* in_sizes, int n_in,
                              void* d_out, int out_size) {
    const float* x   = (const float*)d_in[0];
    const float* kw  = (const float*)d_in[1];
    const float* kb  = (const float*)d_in[2];
    const float* qw  = (const float*)d_in[3];
    const float* qb  = (const float*)d_in[4];
    const float* vw  = (const float*)d_in[5];
    const float* vb  = (const float*)d_in[6];
    const float* ow1 = (const float*)d_in[7];
    const float* ob1 = (const float*)d_in[8];
    const float* bng = (const float*)d_in[9];
    const float* bnb = (const float*)d_in[10];
    const float* ow2 = (const float*)d_in[11];
    const float* ob2 = (const float*)d_in[12];
    const float* gam = (const float*)d_in[13];

    copy_in<<<2048, 256>>>(x);
    for (int l = 0; l < NLAYERS; l++) {
        wconv_qkv<<<dim3(512, 3), 256>>>(kw + l*KHH*CCH, qw + l*KHH*CCH, vw + l*KHH*CCH);
        qkv_gemm<<<dim3(64, 12), 256>>>(kb + l*KHH, qb + l*KHH, vb + l*KHH, l);
        attn_kernel<<<8192, 256>>>(l);
        wconv_c12<<<6912, 256>>>(ow1 + l*CCH*KHH*9, ow2 + l*CCH*CCH*9);
        conv1_gemm<<<dim3(128, 2), 256>>>(ob1 + l*CCH);
        conv2_gemm<<<dim3(128, 2), 256>>>(ob2 + l*CCH, bng + l*CCH, bnb + l*CCH, gam, l);
    }
    copy_out<<<2048, 256>>>((float*)d_out);
}